// round 11
// baseline (speedup 1.0000x reference)
#include <cuda_runtime.h>
#include <cuda_bf16.h>
#include <math.h>

#define BB 65536
#define KK 256
#define DD 128
#define NBLK 444
#define NITER 50
// K'' = 2^13 * K'  (scale-invariant for the Sinkhorn iteration)
#define KADD 8.192e-5f          // 2^13 * 1e-8
#define INVS (1.f / 8192.f)

typedef unsigned long long u64;

// ---- scratch (static device globals; no allocation) ----
__device__ __nv_bfloat16 g_Kh[(size_t)BB * KK];  // K'' in bf16 (32MB) — L2-resident
__device__ float g_ynT[DD * KK];         // normalized prototypes, k-major [k][j]
__device__ float g_xinv[BB];             // 1 / ||x_i||
__device__ float g_a[BB];                // a'' = a / 2^13 (written on last iteration)
__device__ float g_T[3][KK * 32];        // column sums (scale-invariant), 128B apart
__device__ unsigned g_bar;               // grid barrier counter
__device__ double g_sum;

// ---- packed f32x2 helpers ----
__device__ __forceinline__ void fma2(u64& d, u64 a, u64 b) {
    asm("fma.rn.f32x2 %0, %1, %2, %0;" : "+l"(d) : "l"(a), "l"(b));
}
__device__ __forceinline__ u64 add2(u64 a, u64 b) {
    u64 r; asm("add.rn.f32x2 %0, %1, %2;" : "=l"(r) : "l"(a), "l"(b)); return r;
}
__device__ __forceinline__ u64 packff(float lo, float hi) {
    u64 r; asm("mov.b64 %0, {%1, %2};" : "=l"(r) : "f"(lo), "f"(hi)); return r;
}
__device__ __forceinline__ void unpackff(u64 v, float& lo, float& hi) {
    asm("mov.b64 {%0, %1}, %2;" : "=f"(lo), "=f"(hi) : "l"(v));
}
__device__ __forceinline__ u64 pack2(float v) {
    unsigned u = __float_as_uint(v);
    return ((u64)u << 32) | u;
}
// two bf16 in a u32 -> packed f32x2 (bf16->f32 = 16-bit shift)
__device__ __forceinline__ u64 bf2_to_f32x2(unsigned v) {
    unsigned lo = v << 16;
    unsigned hi = v & 0xFFFF0000u;
    u64 r; asm("mov.b64 %0, {%1, %2};" : "=l"(r) : "r"(lo), "r"(hi)); return r;
}
// packed exp2: {2^plo, 2^phi} via one MUFU op (ex2.approx.f16x2)
__device__ __forceinline__ void exp2_h2(float plo, float phi, float& olo, float& ohi) {
    asm("{.reg .b16 l,h;\n\t"
        ".reg .b32 t;\n\t"
        "cvt.rn.f16x2.f32 t, %2, %3;\n\t"   // first src -> high half
        "ex2.approx.f16x2 t, t;\n\t"
        "mov.b32 {l,h}, t;\n\t"
        "cvt.f32.f16 %0, l;\n\t"
        "cvt.f32.f16 %1, h;}\n"
        : "=f"(olo), "=f"(ohi) : "f"(phi), "f"(plo));
}

// ---------------------------------------------------------------------------
__global__ void k_init(const float* __restrict__ proto) {
    int j = threadIdx.x;  // 0..255
    float ss = 0.f;
#pragma unroll 8
    for (int k = 0; k < DD; k++) { float v = proto[j * DD + k]; ss += v * v; }
    float inv = __fdividef(1.f, fmaxf(sqrtf(ss), 1e-12f));
    for (int k = 0; k < DD; k++) g_ynT[k * KK + j] = proto[j * DD + k] * inv;
    const float nuP = 1.f / (float)KK + 1e-8f;
    g_T[0][j * 32] = nuP;   // makes w == 1 on iteration 1 (v0 = 0)
    g_T[1][j * 32] = 0.f;   // accumulation target of iteration 1
    if (j == 0) { g_sum = 0.0; g_bar = 0u; }
}

// ---------------------------------------------------------------------------
__global__ void k_xnorm(const float* __restrict__ x) {
    int warp = threadIdx.x >> 5, lane = threadIdx.x & 31;
    int row = blockIdx.x * 8 + warp;
    float4 v = ((const float4*)(x + (size_t)row * DD))[lane];
    float ss = v.x * v.x + v.y * v.y + v.z * v.z + v.w * v.w;
#pragma unroll
    for (int o = 16; o; o >>= 1) ss += __shfl_xor_sync(0xffffffffu, ss, o);
    if (lane == 0) g_xinv[row] = __fdividef(1.f, fmaxf(sqrtf(ss), 1e-12f));
}

// ---------------------------------------------------------------------------
// cost GEMM via FFMA2; K'' = 2^13*(exp(-10C)+1e-8) in bf16 via packed f16 ex2.
// block = 256 threads, 64 rows x 256 cols, 8x8 tile/thread.
// ---------------------------------------------------------------------------
__global__ void k_gemm(const float* __restrict__ x) {
    __shared__ float ys[32 * 256];  // k-chunk of prototypes [kk][col]  (32KB)
    __shared__ u64 xs2[64 * 32];    // x tile, values duplicated-packed (16KB)

    int t = threadIdx.x;
    int rowBase = blockIdx.x * 64;
    int tx = t & 31, ty = t >> 5;

    u64 acc[8][4];
#pragma unroll
    for (int i = 0; i < 8; i++)
#pragma unroll
        for (int j = 0; j < 4; j++) acc[i][j] = 0ull;

    for (int kc = 0; kc < 4; kc++) {
        __syncthreads();
        {
            const float4* src = (const float4*)(g_ynT + kc * 32 * 256);
            float4* dst = (float4*)ys;
#pragma unroll
            for (int i = 0; i < 8; i++) dst[t + i * 256] = src[t + i * 256];
        }
        {
#pragma unroll
            for (int i = 0; i < 2; i++) {
                int idx = t + i * 256;
                int r = idx >> 3;
                int c4 = idx & 7;
                float4 v = *(const float4*)(x + (size_t)(rowBase + r) * DD + kc * 32 + c4 * 4);
                u64* d = &xs2[r * 32 + c4 * 4];
                d[0] = pack2(v.x); d[1] = pack2(v.y); d[2] = pack2(v.z); d[3] = pack2(v.w);
            }
        }
        __syncthreads();
#pragma unroll 4
        for (int k = 0; k < 32; k++) {
            const ulonglong2* pb = (const ulonglong2*)&ys[k * 256 + tx * 8];
            ulonglong2 b01 = pb[0], b23 = pb[1];
#pragma unroll
            for (int i = 0; i < 8; i++) {
                u64 a2 = xs2[(ty * 8 + i) * 32 + k];   // LDS.64 broadcast
                fma2(acc[i][0], a2, b01.x);
                fma2(acc[i][1], a2, b01.y);
                fma2(acc[i][2], a2, b23.x);
                fma2(acc[i][3], a2, b23.y);
            }
        }
    }

#pragma unroll
    for (int i = 0; i < 8; i++) {
        int row = rowBase + ty * 8 + i;
        float inv = g_xinv[row];
        float kv[8];
#pragma unroll
        for (int j = 0; j < 4; j++) {
            float lo, hi; unpackff(acc[i][j], lo, hi);
            // p = -10*C*log2(e) + 13 ; K'' = 2^p + 2^13*1e-8
            float c0 = 1.f - lo * inv;
            float c1 = 1.f - hi * inv;
            float p0 = fmaf(c0, -14.4269504f, 13.f);
            float p1 = fmaf(c1, -14.4269504f, 13.f);
            float e0, e1;
            exp2_h2(p0, p1, e0, e1);
            kv[2 * j]     = e0 + KADD;
            kv[2 * j + 1] = e1 + KADD;
        }
        __nv_bfloat162 h0 = __float22bfloat162_rn(make_float2(kv[0], kv[1]));
        __nv_bfloat162 h1 = __float22bfloat162_rn(make_float2(kv[2], kv[3]));
        __nv_bfloat162 h2 = __float22bfloat162_rn(make_float2(kv[4], kv[5]));
        __nv_bfloat162 h3 = __float22bfloat162_rn(make_float2(kv[6], kv[7]));
        uint4 s;
        s.x = *(unsigned*)&h0; s.y = *(unsigned*)&h1;
        s.z = *(unsigned*)&h2; s.w = *(unsigned*)&h3;
        *(uint4*)&g_Kh[(size_t)row * KK + tx * 8] = s;
    }
}

// ---------------------------------------------------------------------------
// k_sink helpers: batch = 2 rows; lanes 0-15 -> row 2b, lanes 16-31 -> row 2b+1
// each lane loads 16 bf16 (32B) kept PACKED in 4 u64 regs.
// ---------------------------------------------------------------------------
__device__ __forceinline__ void ldq(int b, int half, int hl, u64* q) {
    const __nv_bfloat16* p = g_Kh + ((size_t)b * 2 + half) * KK + hl * 16;
    asm volatile("ld.global.L2::evict_last.v4.b64 {%0,%1,%2,%3}, [%4];"
                 : "=l"(q[0]), "=l"(q[1]), "=l"(q[2]), "=l"(q[3]) : "l"(p));
}

__device__ __forceinline__ void computeq(int b, int half, int hl, const u64* q,
                                         const u64* w2, u64* tj2, float muP,
                                         bool storeA) {
    u64 pr[8];
#pragma unroll
    for (int i = 0; i < 4; i++) {
        unsigned lo32 = (unsigned)(q[i] & 0xffffffffull);
        unsigned hi32 = (unsigned)(q[i] >> 32);
        pr[2 * i]     = bf2_to_f32x2(lo32);
        pr[2 * i + 1] = bf2_to_f32x2(hi32);
    }
    u64 t0 = 0, t1 = 0, t2 = 0, t3 = 0;
    fma2(t0, pr[0], w2[0]); fma2(t1, pr[1], w2[1]);
    fma2(t2, pr[2], w2[2]); fma2(t3, pr[3], w2[3]);
    fma2(t0, pr[4], w2[4]); fma2(t1, pr[5], w2[5]);
    fma2(t2, pr[6], w2[6]); fma2(t3, pr[7], w2[7]);
    u64 tt = add2(add2(t0, t1), add2(t2, t3));
    float slo, shi; unpackff(tt, slo, shi);
    float s = slo + shi;
#pragma unroll
    for (int o = 8; o; o >>= 1) s += __shfl_xor_sync(0xffffffffu, s, o);
    float a = muP * __fdividef(1.f, s);
    if (storeA && hl == 0) g_a[b * 2 + half] = a;
    u64 a2 = packff(a, a);
#pragma unroll
    for (int k = 0; k < 8; k++) fma2(tj2[k], pr[k], a2);
}

// ---------------------------------------------------------------------------
// ALL 50 Sinkhorn iterations, persistent grid 444 (148 SMs x 3 blocks),
// device grid barrier; bf16 K'', f32x2 math, 2-buffer pipeline.
// ---------------------------------------------------------------------------
__global__ void __launch_bounds__(256, 3) k_sink() {
    const float nuP = 1.f / (float)KK + 1e-8f;
    const float muP = 1.f / (float)BB + 1e-8f;
    __shared__ float Ts2[16 * 256];   // 16 KB: [warp*2+half][col]
    __shared__ float wsh[256];        // per-block w broadcast

    int t = threadIdx.x, lane = t & 31, warp = t >> 5;
    int half = lane >> 4, hl = lane & 15;
    const int nW = NBLK * 8;          // 3552 warps
    const int nB = BB / 2;            // 32768 batches of 2 rows
    int gw = blockIdx.x * 8 + warp;

    for (int it = 1; it <= NITER; it++) {
        int prev = (it - 1) % 3, cur = it % 3, clr = (it + 1) % 3;
        bool last = (it == NITER);

        // w once per block: 1 divide per thread, broadcast via smem
        wsh[t] = nuP * __fdividef(1.f, __ldcg(&g_T[prev][t * 32]));
        __syncthreads();

        u64 w2[8];
        const float2* wp = (const float2*)&wsh[hl * 16];
#pragma unroll
        for (int m = 0; m < 8; m++) w2[m] = packff(wp[m].x, wp[m].y);

        u64 tj2[8];
#pragma unroll
        for (int m = 0; m < 8; m++) tj2[m] = 0ull;

        // 2-buffer pipeline
        u64 qa[4], qb[4];
        ldq(gw, half, hl, qa);
        for (int b = gw; b < nB; b += 2 * nW) {
            int b1 = b + nW, b2 = b + 2 * nW;
            if (b1 < nB) ldq(b1, half, hl, qb);
            computeq(b, half, hl, qa, w2, tj2, muP, last);
            if (b2 < nB) ldq(b2, half, hl, qa);
            if (b1 < nB) computeq(b1, half, hl, qb, w2, tj2, muP, last);
        }

        // clear the buffer that becomes 'cur' next iteration (idle this iter)
        if (blockIdx.x == 0) g_T[clr][t * 32] = 0.f;

        // block-local column reduction, then one global atomic per column
#pragma unroll
        for (int m = 0; m < 8; m++) {
            float lo, hi; unpackff(tj2[m], lo, hi);
            Ts2[(warp * 2 + half) * 256 + hl * 16 + 2 * m] = lo;
            Ts2[(warp * 2 + half) * 256 + hl * 16 + 2 * m + 1] = hi;
        }
        __syncthreads();
        {
            float s = 0.f;
#pragma unroll
            for (int r = 0; r < 16; r++) s += Ts2[r * 256 + t];
            atomicAdd(&g_T[cur][t * 32], s);
        }
        __syncthreads();

        // grid barrier: release-arrive, acquire-spin (monotonic counter)
        if (t == 0) {
            asm volatile("red.release.gpu.global.add.u32 [%0], 1;"
                         :: "l"(&g_bar) : "memory");
            unsigned target = (unsigned)it * NBLK;
            unsigned v;
            while (true) {
                asm volatile("ld.global.acquire.gpu.u32 %0, [%1];"
                             : "=r"(v) : "l"(&g_bar));
                if (v >= target) break;
                __nanosleep(16);
            }
        }
        __syncthreads();
    }
}

// ---------------------------------------------------------------------------
// final: sum_ij a''_i * K''_ij * w_j * C_ij * softmax(|coord_i|)_j
// (a''·K'' = a·K' exactly). C reconstructed: C = -0.1*log(K''/2^13 - 1e-8).
// ---------------------------------------------------------------------------
__global__ void __launch_bounds__(256, 2) k_final(const float* __restrict__ coord, int cur) {
    const float nuP = 1.f / (float)KK + 1e-8f;
    int t = threadIdx.x, lane = t & 31, warp = t >> 5;

    float w[8];
#pragma unroll
    for (int m = 0; m < 8; m++)
        w[m] = nuP * __fdividef(1.f, g_T[cur][(lane * 8 + m) * 32]);

    float accf = 0.f;
    const int nWarps = 296 * 8;
    const int nBatch = BB / 2;   // batches of 2 rows
    int gw = blockIdx.x * 8 + warp;
    int colOff = lane * 8;

    for (int b = gw; b < nBatch; b += nWarps) {
        int row0 = b * 2;
#pragma unroll
        for (int r = 0; r < 2; r++) {
            int row = row0 + r;
            float q[8];
            {
                const float4* Cd = (const float4*)(coord + (size_t)row * KK + colOff);
                float4 c0 = Cd[0], c1 = Cd[1];
                q[0] = fabsf(c0.x); q[1] = fabsf(c0.y); q[2] = fabsf(c0.z); q[3] = fabsf(c0.w);
                q[4] = fabsf(c1.x); q[5] = fabsf(c1.y); q[6] = fabsf(c1.z); q[7] = fabsf(c1.w);
            }
            float mx = q[0];
#pragma unroll
            for (int m = 1; m < 8; m++) mx = fmaxf(mx, q[m]);
#pragma unroll
            for (int o = 16; o; o >>= 1) mx = fmaxf(mx, __shfl_xor_sync(0xffffffffu, mx, o));
            float e[8], z = 0.f;
#pragma unroll
            for (int m = 0; m < 8; m++) { e[m] = __expf(q[m] - mx); z += e[m]; }
#pragma unroll
            for (int o = 16; o; o >>= 1) z += __shfl_xor_sync(0xffffffffu, z, o);
            float rz = __fdividef(1.f, z);

            float a = g_a[row];
            float kk[8];
            {
                uint4 kv = *(const uint4*)&g_Kh[(size_t)row * KK + colOff];
                unsigned u[4] = {kv.x, kv.y, kv.z, kv.w};
#pragma unroll
                for (int i = 0; i < 4; i++) {
                    float2 f2 = __bfloat1622float2(*(__nv_bfloat162*)&u[i]);
                    kk[i * 2] = f2.x; kk[i * 2 + 1] = f2.y;
                }
            }

            float contrib = 0.f;
#pragma unroll
            for (int m = 0; m < 8; m++) {
                float cm = -0.1f * __logf(fmaxf(kk[m] * INVS - 1e-8f, 1e-12f));
                contrib += kk[m] * w[m] * cm * e[m];
            }
            accf += a * rz * contrib;
        }
    }

#pragma unroll
    for (int o = 16; o; o >>= 1) accf += __shfl_xor_sync(0xffffffffu, accf, o);
    __shared__ double sw[8];
    if (lane == 0) sw[warp] = (double)accf;
    __syncthreads();
    if (t == 0) {
        double s = 0.0;
#pragma unroll
        for (int i = 0; i < 8; i++) s += sw[i];
        atomicAdd(&g_sum, s);
    }
}

__global__ void k_write(float* out) { out[0] = (float)g_sum; }

// ---------------------------------------------------------------------------
extern "C" void kernel_launch(void* const* d_in, const int* in_sizes, int n_in,
                              void* d_out, int out_size) {
    const float* x     = (const float*)d_in[0];   // (65536, 128)
    const float* proto = (const float*)d_in[1];   // (256, 128)
    const float* coord = (const float*)d_in[2];   // (65536, 256)

    k_init<<<1, 256>>>(proto);
    k_xnorm<<<BB / 8, 256>>>(x);
    k_gemm<<<BB / 64, 256>>>(x);

    k_sink<<<NBLK, 256>>>();

    k_final<<<296, 256>>>(coord, NITER % 3);
    k_write<<<1, 1>>>((float*)d_out);
}

// round 14
// speedup vs baseline: 1.0761x; 1.0761x over previous
#include <cuda_runtime.h>
#include <cuda_bf16.h>
#include <math.h>

#define BB 65536
#define KK 256
#define DD 128
#define NITER 50
#define SNBLK 148          // k_sink: one persistent block per SM
#define SROWS 434          // smem-resident rows per block
#define SBATCH 217         // 2-row batches per block (smem)
#define GSTART (SNBLK * SROWS)          // 64232: first global-resident row
#define GBATCH ((BB - GSTART) / 2)      // 652 leftover 2-row batches
#define TS_OFF (SROWS * 512)            // 222208
#define WSH_OFF (TS_OFF + 8192)         // 230400
#define SMEM_SINK (WSH_OFF + 1024)      // 231424 B = 226 KB

typedef unsigned long long u64;

// ---- scratch (static device globals; no allocation) ----
__device__ __nv_bfloat16 g_Kh[(size_t)BB * KK];  // K' in bf16 (32MB)
__device__ float g_ynT[DD * KK];         // normalized prototypes, k-major [k][j]
__device__ float g_xinv[BB];             // 1 / ||x_i||
__device__ float g_a[BB];                // exp(u)   (written on last iteration)
__device__ float g_T[3][KK * 32];        // column sums, padded 128B apart
__device__ unsigned g_bar;               // grid barrier counter
__device__ double g_sum;

// ---- packed f32x2 helpers ----
__device__ __forceinline__ void fma2(u64& d, u64 a, u64 b) {
    asm("fma.rn.f32x2 %0, %1, %2, %0;" : "+l"(d) : "l"(a), "l"(b));
}
__device__ __forceinline__ u64 add2(u64 a, u64 b) {
    u64 r; asm("add.rn.f32x2 %0, %1, %2;" : "=l"(r) : "l"(a), "l"(b)); return r;
}
__device__ __forceinline__ u64 packff(float lo, float hi) {
    u64 r; asm("mov.b64 %0, {%1, %2};" : "=l"(r) : "f"(lo), "f"(hi)); return r;
}
__device__ __forceinline__ void unpackff(u64 v, float& lo, float& hi) {
    asm("mov.b64 {%0, %1}, %2;" : "=f"(lo), "=f"(hi) : "l"(v));
}
__device__ __forceinline__ u64 bf2_to_f32x2(unsigned v) {
    unsigned lo = v << 16;
    unsigned hi = v & 0xFFFF0000u;
    u64 r; asm("mov.b64 %0, {%1, %2};" : "=l"(r) : "r"(lo), "r"(hi)); return r;
}

// ---------------------------------------------------------------------------
__global__ void k_init(const float* __restrict__ proto) {
    int j = threadIdx.x;  // 0..255
    float ss = 0.f;
#pragma unroll 8
    for (int k = 0; k < DD; k++) { float v = proto[j * DD + k]; ss += v * v; }
    float inv = __fdividef(1.f, fmaxf(sqrtf(ss), 1e-12f));
    for (int k = 0; k < DD; k++) g_ynT[k * KK + j] = proto[j * DD + k] * inv;
    const float nuP = 1.f / (float)KK + 1e-8f;
    g_T[0][j * 32] = nuP;   // makes w == 1 on iteration 1 (v0 = 0)
    g_T[1][j * 32] = 0.f;   // accumulation target of iteration 1
    if (j == 0) { g_sum = 0.0; g_bar = 0u; }
}

// ---------------------------------------------------------------------------
__global__ void k_xnorm(const float* __restrict__ x) {
    int warp = threadIdx.x >> 5, lane = threadIdx.x & 31;
    int row = blockIdx.x * 8 + warp;
    float4 v = ((const float4*)(x + (size_t)row * DD))[lane];
    float ss = v.x * v.x + v.y * v.y + v.z * v.z + v.w * v.w;
#pragma unroll
    for (int o = 16; o; o >>= 1) ss += __shfl_xor_sync(0xffffffffu, ss, o);
    if (lane == 0) g_xinv[row] = __fdividef(1.f, fmaxf(sqrtf(ss), 1e-12f));
}

// ---------------------------------------------------------------------------
// cost GEMM (R10 — proven): FFMA2; K' = exp(-10*(1 - xn.yn)) + 1e-8, bf16.
// ---------------------------------------------------------------------------
__global__ void k_gemm(const float* __restrict__ x) {
    __shared__ float ys[32 * 256];
    __shared__ float xs[64 * 32];
    __shared__ float xrn[64];

    int t = threadIdx.x;
    int rowBase = blockIdx.x * 64;
    if (t < 64) xrn[t] = g_xinv[rowBase + t];

    int tx = t & 31, ty = t >> 5;
    u64 acc[8][4];
#pragma unroll
    for (int i = 0; i < 8; i++)
#pragma unroll
        for (int j = 0; j < 4; j++) acc[i][j] = 0ull;

    for (int kc = 0; kc < 4; kc++) {
        __syncthreads();
        {
            const float4* src = (const float4*)(g_ynT + kc * 32 * 256);
            float4* dst = (float4*)ys;
#pragma unroll
            for (int i = 0; i < 8; i++) dst[t + i * 256] = src[t + i * 256];
        }
        {
#pragma unroll
            for (int i = 0; i < 2; i++) {
                int idx = t + i * 256;
                int r = idx >> 3;
                int c4 = idx & 7;
                float4 v = *(const float4*)(x + (size_t)(rowBase + r) * DD + kc * 32 + c4 * 4);
                *(float4*)&xs[r * 32 + c4 * 4] = v;
            }
        }
        __syncthreads();
#pragma unroll 4
        for (int k = 0; k < 32; k++) {
            float4 b0 = *(const float4*)&ys[k * 256 + tx * 8];
            float4 b1 = *(const float4*)&ys[k * 256 + tx * 8 + 4];
            u64 p0 = packff(b0.x, b0.y), p1 = packff(b0.z, b0.w);
            u64 p2 = packff(b1.x, b1.y), p3 = packff(b1.z, b1.w);
#pragma unroll
            for (int i = 0; i < 8; i++) {
                float a = xs[(ty * 8 + i) * 32 + k];
                u64 a2 = packff(a, a);
                fma2(acc[i][0], a2, p0);
                fma2(acc[i][1], a2, p1);
                fma2(acc[i][2], a2, p2);
                fma2(acc[i][3], a2, p3);
            }
        }
    }

#pragma unroll
    for (int i = 0; i < 8; i++) {
        int row = rowBase + ty * 8 + i;
        float inv = xrn[ty * 8 + i];
        float kv[8];
#pragma unroll
        for (int j = 0; j < 4; j++) {
            float lo, hi; unpackff(acc[i][j], lo, hi);
            float c0 = 1.f - lo * inv;
            float c1 = 1.f - hi * inv;
            kv[2 * j]     = __expf(-10.f * c0) + 1e-8f;
            kv[2 * j + 1] = __expf(-10.f * c1) + 1e-8f;
        }
        __nv_bfloat162 h0 = __float22bfloat162_rn(make_float2(kv[0], kv[1]));
        __nv_bfloat162 h1 = __float22bfloat162_rn(make_float2(kv[2], kv[3]));
        __nv_bfloat162 h2 = __float22bfloat162_rn(make_float2(kv[4], kv[5]));
        __nv_bfloat162 h3 = __float22bfloat162_rn(make_float2(kv[6], kv[7]));
        uint4 s;
        s.x = *(unsigned*)&h0; s.y = *(unsigned*)&h1;
        s.z = *(unsigned*)&h2; s.w = *(unsigned*)&h3;
        *(uint4*)&g_Kh[(size_t)row * KK + tx * 8] = s;
    }
}

// ---------------------------------------------------------------------------
// shared compute for one row-half (16 bf16 in q[4]): s-reduce over the 16-lane
// half, a = mu/s, tj += K*a. Row index explicit.
// ---------------------------------------------------------------------------
__device__ __forceinline__ void comp_row(int row, const u64* q, const u64* w2,
                                         u64* tj2, float muP, bool storeA, int hl) {
    u64 pr[8];
#pragma unroll
    for (int i = 0; i < 4; i++) {
        unsigned lo32 = (unsigned)(q[i] & 0xffffffffull);
        unsigned hi32 = (unsigned)(q[i] >> 32);
        pr[2 * i]     = bf2_to_f32x2(lo32);
        pr[2 * i + 1] = bf2_to_f32x2(hi32);
    }
    u64 t0 = 0, t1 = 0, t2 = 0, t3 = 0;
    fma2(t0, pr[0], w2[0]); fma2(t1, pr[1], w2[1]);
    fma2(t2, pr[2], w2[2]); fma2(t3, pr[3], w2[3]);
    fma2(t0, pr[4], w2[4]); fma2(t1, pr[5], w2[5]);
    fma2(t2, pr[6], w2[6]); fma2(t3, pr[7], w2[7]);
    u64 tt = add2(add2(t0, t1), add2(t2, t3));
    float slo, shi; unpackff(tt, slo, shi);
    float s = slo + shi;
#pragma unroll
    for (int o = 8; o; o >>= 1) s += __shfl_xor_sync(0xffffffffu, s, o);
    float a = muP * __fdividef(1.f, s);
    if (storeA && hl == 0) g_a[row] = a;
    u64 a2 = packff(a, a);
#pragma unroll
    for (int k = 0; k < 8; k++) fma2(tj2[k], pr[k], a2);
}

__device__ __forceinline__ void ldq_g(int row, int hl, u64* q) {
    const __nv_bfloat16* p = g_Kh + (size_t)row * KK + hl * 16;
    asm volatile("ld.global.L2::evict_last.v4.b64 {%0,%1,%2,%3}, [%4];"
                 : "=l"(q[0]), "=l"(q[1]), "=l"(q[2]), "=l"(q[3]) : "l"(p));
}

// ---------------------------------------------------------------------------
// ALL 50 Sinkhorn iterations. 148 persistent blocks x 1024 threads (1/SM).
// Each block holds 434 rows of K in SMEM (217KB); 1304 leftover rows from L2.
// ---------------------------------------------------------------------------
__global__ void __launch_bounds__(1024, 1) k_sink() {
    extern __shared__ char sm[];
    float* Ts  = (float*)(sm + TS_OFF);    // 8 x 256 f32 staging
    float* wsh = (float*)(sm + WSH_OFF);   // 256 f32 w broadcast

    const float nuP = 1.f / (float)KK + 1e-8f;
    const float muP = 1.f / (float)BB + 1e-8f;
    int t = threadIdx.x, lane = t & 31, warp = t >> 5;
    int half = lane >> 4, hl = lane & 15;
    int rowBase = blockIdx.x * SROWS;

    // one-time fill: this block's K slab, global -> smem (coalesced uint4)
    {
        const uint4* src = (const uint4*)(g_Kh + (size_t)rowBase * KK);
        uint4* dst = (uint4*)sm;
        for (int i = t; i < SROWS * 32; i += 1024) dst[i] = src[i];
    }
    __syncthreads();

    for (int it = 1; it <= NITER; it++) {
        int prev = (it - 1) % 3, cur = it % 3, clr = (it + 1) % 3;
        bool last = (it == NITER);

        if (t < 256) wsh[t] = nuP * __fdividef(1.f, __ldcg(&g_T[prev][t * 32]));
        __syncthreads();

        u64 w2[8];
        const float2* wp = (const float2*)&wsh[hl * 16];
#pragma unroll
        for (int m = 0; m < 8; m++) w2[m] = packff(wp[m].x, wp[m].y);

        u64 tj2[8];
#pragma unroll
        for (int m = 0; m < 8; m++) tj2[m] = 0ull;

        // smem-resident batches (2 rows each; halves of the warp split rows)
        for (int lb = warp; lb < SBATCH; lb += 32) {
            const ulonglong2* p =
                (const ulonglong2*)(sm + (lb * 2 + half) * 512 + hl * 32);
            ulonglong2 qa = p[0], qb = p[1];
            u64 q[4] = {qa.x, qa.y, qb.x, qb.y};
            comp_row(rowBase + lb * 2 + half, q, w2, tj2, muP, last, hl);
        }
        // leftover global batches (high warps take them to balance load)
        {
            int j = 31 - warp;
            if (j < 5) {
                int gidx = blockIdx.x + SNBLK * j;
                if (gidx < GBATCH) {
                    int row = GSTART + gidx * 2 + half;
                    u64 q[4];
                    ldq_g(row, hl, q);
                    comp_row(row, q, w2, tj2, muP, last, hl);
                }
            }
        }

        // combine the two 16-lane halves (they own the same 16 columns)
#pragma unroll
        for (int m = 0; m < 8; m++) {
            u64 o = __shfl_xor_sync(0xffffffffu, tj2[m], 16);
            tj2[m] = add2(tj2[m], o);
        }

        // staged cross-warp reduction: 4 rounds x 8 warps through 8KB buffer
        float accT = 0.f;
#pragma unroll 1
        for (int r = 0; r < 4; r++) {
            if ((warp >> 3) == r && half == 0) {
                u64* dstT = (u64*)&Ts[(warp & 7) * 256 + hl * 16];
#pragma unroll
                for (int m = 0; m < 8; m++) dstT[m] = tj2[m];
            }
            __syncthreads();
            if (t < 256) {
#pragma unroll
                for (int rr = 0; rr < 8; rr++) accT += Ts[rr * 256 + t];
            }
            __syncthreads();
        }

        if (blockIdx.x == 0 && t < 256) g_T[clr][t * 32] = 0.f;
        if (t < 256) atomicAdd(&g_T[cur][t * 32], accT);
        __syncthreads();

        // grid barrier: release-arrive, acquire-spin (monotonic counter)
        if (t == 0) {
            asm volatile("red.release.gpu.global.add.u32 [%0], 1;"
                         :: "l"(&g_bar) : "memory");
            unsigned target = (unsigned)it * SNBLK;
            unsigned v;
            while (true) {
                asm volatile("ld.global.acquire.gpu.u32 %0, [%1];"
                             : "=r"(v) : "l"(&g_bar));
                if (v >= target) break;
                __nanosleep(16);
            }
        }
        __syncthreads();
    }
}

// ---------------------------------------------------------------------------
// final: sum_ij a_i * K'_ij * w_j * C_ij * softmax(|coord_i|)_j
// C reconstructed: C = -0.1 * log(K' - 1e-8).
// ---------------------------------------------------------------------------
__global__ void __launch_bounds__(256, 2) k_final(const float* __restrict__ coord, int cur) {
    const float nuP = 1.f / (float)KK + 1e-8f;
    int t = threadIdx.x, lane = t & 31, warp = t >> 5;

    float w[8];
#pragma unroll
    for (int m = 0; m < 8; m++)
        w[m] = nuP * __fdividef(1.f, g_T[cur][(lane * 8 + m) * 32]);

    float accf = 0.f;
    const int nWarps = 296 * 8;
    const int nBatch = BB / 2;
    int gw = blockIdx.x * 8 + warp;
    int colOff = lane * 8;

    for (int b = gw; b < nBatch; b += nWarps) {
        int row0 = b * 2;
#pragma unroll
        for (int r = 0; r < 2; r++) {
            int row = row0 + r;
            float q[8];
            {
                const float4* Cd = (const float4*)(coord + (size_t)row * KK + colOff);
                float4 c0 = Cd[0], c1 = Cd[1];
                q[0] = fabsf(c0.x); q[1] = fabsf(c0.y); q[2] = fabsf(c0.z); q[3] = fabsf(c0.w);
                q[4] = fabsf(c1.x); q[5] = fabsf(c1.y); q[6] = fabsf(c1.z); q[7] = fabsf(c1.w);
            }
            float mx = q[0];
#pragma unroll
            for (int m = 1; m < 8; m++) mx = fmaxf(mx, q[m]);
#pragma unroll
            for (int o = 16; o; o >>= 1) mx = fmaxf(mx, __shfl_xor_sync(0xffffffffu, mx, o));
            float e[8], z = 0.f;
#pragma unroll
            for (int m = 0; m < 8; m++) { e[m] = __expf(q[m] - mx); z += e[m]; }
#pragma unroll
            for (int o = 16; o; o >>= 1) z += __shfl_xor_sync(0xffffffffu, z, o);
            float rz = __fdividef(1.f, z);

            float a = g_a[row];
            float kk[8];
            {
                uint4 kv = *(const uint4*)&g_Kh[(size_t)row * KK + colOff];
                unsigned u[4] = {kv.x, kv.y, kv.z, kv.w};
#pragma unroll
                for (int i = 0; i < 4; i++) {
                    float2 f2 = __bfloat1622float2(*(__nv_bfloat162*)&u[i]);
                    kk[i * 2] = f2.x; kk[i * 2 + 1] = f2.y;
                }
            }

            float contrib = 0.f;
#pragma unroll
            for (int m = 0; m < 8; m++) {
                float cm = -0.1f * __logf(fmaxf(kk[m] - 1e-8f, 1e-12f));
                contrib += kk[m] * w[m] * cm * e[m];
            }
            accf += a * rz * contrib;
        }
    }

#pragma unroll
    for (int o = 16; o; o >>= 1) accf += __shfl_xor_sync(0xffffffffu, accf, o);
    __shared__ double sw[8];
    if (lane == 0) sw[warp] = (double)accf;
    __syncthreads();
    if (t == 0) {
        double s = 0.0;
#pragma unroll
        for (int i = 0; i < 8; i++) s += sw[i];
        atomicAdd(&g_sum, s);
    }
}

__global__ void k_write(float* out) { out[0] = (float)g_sum; }

// ---------------------------------------------------------------------------
extern "C" void kernel_launch(void* const* d_in, const int* in_sizes, int n_in,
                              void* d_out, int out_size) {
    const float* x     = (const float*)d_in[0];   // (65536, 128)
    const float* proto = (const float*)d_in[1];   // (256, 128)
    const float* coord = (const float*)d_in[2];   // (65536, 256)

    cudaFuncSetAttribute(k_sink, cudaFuncAttributeMaxDynamicSharedMemorySize,
                         SMEM_SINK);

    k_init<<<1, 256>>>(proto);
    k_xnorm<<<BB / 8, 256>>>(x);
    k_gemm<<<BB / 64, 256>>>(x);

    k_sink<<<SNBLK, 1024, SMEM_SINK>>>();

    k_final<<<296, 256>>>(coord, NITER % 3);
    k_write<<<1, 1>>>((float*)d_out);
}